// round 3
// baseline (speedup 1.0000x reference)
#include <cuda_runtime.h>
#include <cuda_bf16.h>
#include <cstdint>

// Problem constants
#define BATCH   2
#define TSEQ    2048
#define CDIM    1024
#define NHEADS  16
#define HDIM    64          // CDIM / NHEADS
#define QKVN    (3 * CDIM)  // 3072

// Scratch (allocation-free rule: __device__ globals)
__device__ float g_qkv[(size_t)BATCH * TSEQ * 3 * CDIM];  // (B,T,3,H,D) flattened: 48 MB
__device__ float g_att[(size_t)BATCH * TSEQ * CDIM];      // attention out (B,T,C): 16 MB

// ---------------------------------------------------------------------------
// SGEMM:  C[M,N] = A[M,K] @ B[K,N] + bias[N]
// BM=128, BN=128, BK=8, TM=8, TN=8, 256 threads
// ---------------------------------------------------------------------------
__global__ __launch_bounds__(256) void sgemm_bias_kernel(
    const float* __restrict__ A, const float* __restrict__ B,
    const float* __restrict__ bias, float* __restrict__ C,
    int M, int N, int K)
{
    const int BM = 128, BN = 128, BK = 8, TM = 8, TN = 8;
    __shared__ float As[BK][BM];
    __shared__ float Bs[BK][BN];

    const int tid = threadIdx.x;
    const int bm  = blockIdx.y * BM;
    const int bn  = blockIdx.x * BN;

    const int tx = tid % (BN / TN);   // 0..15
    const int ty = tid / (BN / TN);   // 0..15

    // A-tile loader: 128x8 floats = 256 float4; one float4 per thread
    const int arow = tid / 2;             // 0..127
    const int acol = (tid % 2) * 4;       // 0 or 4
    // B-tile loader: 8x128 floats = 256 float4
    const int brow = tid / 32;            // 0..7
    const int bcol = (tid % 32) * 4;      // 0..124

    float acc[TM][TN];
    #pragma unroll
    for (int i = 0; i < TM; i++)
        #pragma unroll
        for (int j = 0; j < TN; j++)
            acc[i][j] = 0.0f;

    for (int k0 = 0; k0 < K; k0 += BK) {
        float4 av = *(const float4*)&A[(size_t)(bm + arow) * K + k0 + acol];
        float4 bv = *(const float4*)&B[(size_t)(k0 + brow) * N + bn + bcol];
        __syncthreads();
        As[acol + 0][arow] = av.x;
        As[acol + 1][arow] = av.y;
        As[acol + 2][arow] = av.z;
        As[acol + 3][arow] = av.w;
        *(float4*)&Bs[brow][bcol] = bv;
        __syncthreads();

        #pragma unroll
        for (int kk = 0; kk < BK; kk++) {
            float ar[TM], br[TN];
            #pragma unroll
            for (int i = 0; i < TM; i++) ar[i] = As[kk][ty * TM + i];
            #pragma unroll
            for (int j = 0; j < TN; j++) br[j] = Bs[kk][tx * TN + j];
            #pragma unroll
            for (int i = 0; i < TM; i++)
                #pragma unroll
                for (int j = 0; j < TN; j++)
                    acc[i][j] += ar[i] * br[j];
        }
    }

    // Epilogue: add bias, store as float4 (8 contiguous cols per thread)
    #pragma unroll
    for (int i = 0; i < TM; i++) {
        const int row = bm + ty * TM + i;
        const int col = bn + tx * TN;
        float out[TN];
        #pragma unroll
        for (int j = 0; j < TN; j++) out[j] = acc[i][j] + bias[col + j];
        *(float4*)&C[(size_t)row * N + col]     = *(float4*)&out[0];
        *(float4*)&C[(size_t)row * N + col + 4] = *(float4*)&out[4];
    }
}

// ---------------------------------------------------------------------------
// Flash attention (fp32). One CTA = one (b, h, 128-query tile).
// 128 threads; thread t owns query row (qt*128 + t): q[64] and acc[64] in regs.
// K/V tiles of 32 keys in shared memory (broadcast reads, conflict-free).
// Online softmax with per-tile max.
// ---------------------------------------------------------------------------
#define KTILE 32

__global__ __launch_bounds__(128) void flash_attn_kernel(
    const float* __restrict__ qkv, float* __restrict__ out)
{
    const int b  = blockIdx.z;
    const int h  = blockIdx.y;
    const int qt = blockIdx.x;
    const int tid = threadIdx.x;
    const int qrow = qt * 128 + tid;

    __shared__ float ks[KTILE][HDIM];
    __shared__ float vs[KTILE][HDIM];
    __shared__ float sbuf[128][KTILE + 1];   // pad: stride 33 -> conflict-free

    // Load q row, pre-scale by D^-0.5
    float q[HDIM];
    {
        const float* qp = qkv + ((size_t)(b * TSEQ + qrow)) * (3 * CDIM) + h * HDIM;
        #pragma unroll
        for (int d = 0; d < HDIM; d += 4) {
            float4 v4 = *(const float4*)&qp[d];
            q[d + 0] = v4.x * 0.125f;
            q[d + 1] = v4.y * 0.125f;
            q[d + 2] = v4.z * 0.125f;
            q[d + 3] = v4.w * 0.125f;
        }
    }

    float m = -1e30f, l = 0.0f;
    float acc[HDIM];
    #pragma unroll
    for (int d = 0; d < HDIM; d++) acc[d] = 0.0f;

    for (int kt = 0; kt < TSEQ; kt += KTILE) {
        __syncthreads();   // previous tile fully consumed
        // Cooperative K/V tile load: 32 rows x 64 floats = 512 float4 per tensor
        // 128 threads -> 4 float4 each per tensor
        for (int i = tid; i < KTILE * (HDIM / 4); i += 128) {
            const int row = i / (HDIM / 4);
            const int c4  = (i % (HDIM / 4)) * 4;
            const size_t base = ((size_t)(b * TSEQ + kt + row)) * (3 * CDIM) + h * HDIM + c4;
            *(float4*)&ks[row][c4] = *(const float4*)&qkv[base + CDIM];       // s=1 (K)
            *(float4*)&vs[row][c4] = *(const float4*)&qkv[base + 2 * CDIM];   // s=2 (V)
        }
        __syncthreads();

        // Pass 1: scores + tile max
        float tmax = -1e30f;
        #pragma unroll 4
        for (int j = 0; j < KTILE; j++) {
            float s = 0.0f;
            #pragma unroll
            for (int d = 0; d < HDIM; d++) s += q[d] * ks[j][d];
            sbuf[tid][j] = s;
            tmax = fmaxf(tmax, s);
        }

        const float mnew = fmaxf(m, tmax);
        const float corr = __expf(m - mnew);
        l *= corr;
        #pragma unroll
        for (int d = 0; d < HDIM; d++) acc[d] *= corr;
        m = mnew;

        // Pass 2: exp + AV accumulate
        for (int j = 0; j < KTILE; j++) {
            const float p = __expf(sbuf[tid][j] - mnew);
            l += p;
            #pragma unroll
            for (int d = 0; d < HDIM; d++) acc[d] += p * vs[j][d];
        }
    }

    const float inv = 1.0f / l;
    float* op = out + ((size_t)(b * TSEQ + qrow)) * CDIM + h * HDIM;
    #pragma unroll
    for (int d = 0; d < HDIM; d += 4) {
        float4 v4;
        v4.x = acc[d + 0] * inv;
        v4.y = acc[d + 1] * inv;
        v4.z = acc[d + 2] * inv;
        v4.w = acc[d + 3] * inv;
        *(float4*)&op[d] = v4;
    }
}

// ---------------------------------------------------------------------------
// Launch
// ---------------------------------------------------------------------------
extern "C" void kernel_launch(void* const* d_in, const int* in_sizes, int n_in,
                              void* d_out, int out_size)
{
    const float* x      = (const float*)d_in[0];  // (B,T,C)
    const float* w_qkv  = (const float*)d_in[1];  // (C, 3C)
    const float* b_qkv  = (const float*)d_in[2];  // (3C)
    const float* w_proj = (const float*)d_in[3];  // (C, C)
    const float* b_proj = (const float*)d_in[4];  // (C)
    float* out = (float*)d_out;                   // (B,T,C)

    float* qkv; cudaGetSymbolAddress((void**)&qkv, g_qkv);
    float* att; cudaGetSymbolAddress((void**)&att, g_att);

    const int M = BATCH * TSEQ;   // 4096

    // 1) QKV projection: (4096,1024) @ (1024,3072) + bias
    {
        dim3 grid(QKVN / 128, M / 128);   // (24, 32)
        sgemm_bias_kernel<<<grid, 256>>>(x, w_qkv, b_qkv, qkv, M, QKVN, CDIM);
    }

    // 2) Flash attention -> g_att (B,T,C)
    {
        dim3 grid(TSEQ / 128, NHEADS, BATCH);   // (16, 16, 2)
        flash_attn_kernel<<<grid, 128>>>(qkv, att);
    }

    // 3) Output projection: (4096,1024) @ (1024,1024) + bias
    {
        dim3 grid(CDIM / 128, M / 128);   // (8, 32)
        sgemm_bias_kernel<<<grid, 256>>>(att, w_proj, b_proj, out, M, CDIM, CDIM);
    }
}

// round 4
// speedup vs baseline: 1.0011x; 1.0011x over previous
#include <cuda_runtime.h>
#include <cuda_bf16.h>
#include <cstdint>

// Problem constants
#define BATCH   2
#define TSEQ    2048
#define CDIM    1024
#define NHEADS  16
#define HDIM    64          // CDIM / NHEADS
#define QKVN    (3 * CDIM)  // 3072

// Scratch (allocation-free rule: __device__ globals)
__device__ float g_qkv[(size_t)BATCH * TSEQ * 3 * CDIM];  // (B,T,3,H,D) flattened: 48 MB
__device__ float g_att[(size_t)BATCH * TSEQ * CDIM];      // attention out (B,T,C): 16 MB

// ---------------------------------------------------------------------------
// SGEMM:  C[M,N] = A[M,K] @ B[K,N] + bias[N]
// BM=128, BN=128, BK=8, TM=8, TN=8, 256 threads
// ---------------------------------------------------------------------------
__global__ __launch_bounds__(256) void sgemm_bias_kernel(
    const float* __restrict__ A, const float* __restrict__ B,
    const float* __restrict__ bias, float* __restrict__ C,
    int M, int N, int K)
{
    const int BM = 128, BN = 128, BK = 8, TM = 8, TN = 8;
    __shared__ float As[BK][BM];
    __shared__ float Bs[BK][BN];

    const int tid = threadIdx.x;
    const int bm  = blockIdx.y * BM;
    const int bn  = blockIdx.x * BN;

    const int tx = tid % (BN / TN);   // 0..15
    const int ty = tid / (BN / TN);   // 0..15

    // A-tile loader: 128x8 floats = 256 float4; one float4 per thread
    const int arow = tid / 2;             // 0..127
    const int acol = (tid % 2) * 4;       // 0 or 4
    // B-tile loader: 8x128 floats = 256 float4
    const int brow = tid / 32;            // 0..7
    const int bcol = (tid % 32) * 4;      // 0..124

    float acc[TM][TN];
    #pragma unroll
    for (int i = 0; i < TM; i++)
        #pragma unroll
        for (int j = 0; j < TN; j++)
            acc[i][j] = 0.0f;

    for (int k0 = 0; k0 < K; k0 += BK) {
        float4 av = *(const float4*)&A[(size_t)(bm + arow) * K + k0 + acol];
        float4 bv = *(const float4*)&B[(size_t)(k0 + brow) * N + bn + bcol];
        __syncthreads();
        As[acol + 0][arow] = av.x;
        As[acol + 1][arow] = av.y;
        As[acol + 2][arow] = av.z;
        As[acol + 3][arow] = av.w;
        *(float4*)&Bs[brow][bcol] = bv;
        __syncthreads();

        #pragma unroll
        for (int kk = 0; kk < BK; kk++) {
            float ar[TM], br[TN];
            #pragma unroll
            for (int i = 0; i < TM; i++) ar[i] = As[kk][ty * TM + i];
            #pragma unroll
            for (int j = 0; j < TN; j++) br[j] = Bs[kk][tx * TN + j];
            #pragma unroll
            for (int i = 0; i < TM; i++)
                #pragma unroll
                for (int j = 0; j < TN; j++)
                    acc[i][j] += ar[i] * br[j];
        }
    }

    // Epilogue: add bias, store as float4 (8 contiguous cols per thread)
    #pragma unroll
    for (int i = 0; i < TM; i++) {
        const int row = bm + ty * TM + i;
        const int col = bn + tx * TN;
        float out[TN];
        #pragma unroll
        for (int j = 0; j < TN; j++) out[j] = acc[i][j] + bias[col + j];
        *(float4*)&C[(size_t)row * N + col]     = *(float4*)&out[0];
        *(float4*)&C[(size_t)row * N + col + 4] = *(float4*)&out[4];
    }
}

// ---------------------------------------------------------------------------
// Flash attention (fp32). One CTA = one (b, h, 128-query tile).
// 128 threads; thread t owns query row (qt*128 + t): q[64] and acc[64] in regs.
// K/V tiles of 32 keys in shared memory (broadcast reads, conflict-free).
// Online softmax with per-tile max.
// ---------------------------------------------------------------------------
#define KTILE 32

__global__ __launch_bounds__(128) void flash_attn_kernel(
    const float* __restrict__ qkv, float* __restrict__ out)
{
    const int b  = blockIdx.z;
    const int h  = blockIdx.y;
    const int qt = blockIdx.x;
    const int tid = threadIdx.x;
    const int qrow = qt * 128 + tid;

    __shared__ float ks[KTILE][HDIM];
    __shared__ float vs[KTILE][HDIM];
    __shared__ float sbuf[128][KTILE + 1];   // pad: stride 33 -> conflict-free

    // Load q row, pre-scale by D^-0.5
    float q[HDIM];
    {
        const float* qp = qkv + ((size_t)(b * TSEQ + qrow)) * (3 * CDIM) + h * HDIM;
        #pragma unroll
        for (int d = 0; d < HDIM; d += 4) {
            float4 v4 = *(const float4*)&qp[d];
            q[d + 0] = v4.x * 0.125f;
            q[d + 1] = v4.y * 0.125f;
            q[d + 2] = v4.z * 0.125f;
            q[d + 3] = v4.w * 0.125f;
        }
    }

    float m = -1e30f, l = 0.0f;
    float acc[HDIM];
    #pragma unroll
    for (int d = 0; d < HDIM; d++) acc[d] = 0.0f;

    for (int kt = 0; kt < TSEQ; kt += KTILE) {
        __syncthreads();   // previous tile fully consumed
        // Cooperative K/V tile load: 32 rows x 64 floats = 512 float4 per tensor
        // 128 threads -> 4 float4 each per tensor
        for (int i = tid; i < KTILE * (HDIM / 4); i += 128) {
            const int row = i / (HDIM / 4);
            const int c4  = (i % (HDIM / 4)) * 4;
            const size_t base = ((size_t)(b * TSEQ + kt + row)) * (3 * CDIM) + h * HDIM + c4;
            *(float4*)&ks[row][c4] = *(const float4*)&qkv[base + CDIM];       // s=1 (K)
            *(float4*)&vs[row][c4] = *(const float4*)&qkv[base + 2 * CDIM];   // s=2 (V)
        }
        __syncthreads();

        // Pass 1: scores + tile max
        float tmax = -1e30f;
        #pragma unroll 4
        for (int j = 0; j < KTILE; j++) {
            float s = 0.0f;
            #pragma unroll
            for (int d = 0; d < HDIM; d++) s += q[d] * ks[j][d];
            sbuf[tid][j] = s;
            tmax = fmaxf(tmax, s);
        }

        const float mnew = fmaxf(m, tmax);
        const float corr = __expf(m - mnew);
        l *= corr;
        #pragma unroll
        for (int d = 0; d < HDIM; d++) acc[d] *= corr;
        m = mnew;

        // Pass 2: exp + AV accumulate
        for (int j = 0; j < KTILE; j++) {
            const float p = __expf(sbuf[tid][j] - mnew);
            l += p;
            #pragma unroll
            for (int d = 0; d < HDIM; d++) acc[d] += p * vs[j][d];
        }
    }

    const float inv = 1.0f / l;
    float* op = out + ((size_t)(b * TSEQ + qrow)) * CDIM + h * HDIM;
    #pragma unroll
    for (int d = 0; d < HDIM; d += 4) {
        float4 v4;
        v4.x = acc[d + 0] * inv;
        v4.y = acc[d + 1] * inv;
        v4.z = acc[d + 2] * inv;
        v4.w = acc[d + 3] * inv;
        *(float4*)&op[d] = v4;
    }
}

// ---------------------------------------------------------------------------
// Launch
// ---------------------------------------------------------------------------
extern "C" void kernel_launch(void* const* d_in, const int* in_sizes, int n_in,
                              void* d_out, int out_size)
{
    const float* x      = (const float*)d_in[0];  // (B,T,C)
    const float* w_qkv  = (const float*)d_in[1];  // (C, 3C)
    const float* b_qkv  = (const float*)d_in[2];  // (3C)
    const float* w_proj = (const float*)d_in[3];  // (C, C)
    const float* b_proj = (const float*)d_in[4];  // (C)
    float* out = (float*)d_out;                   // (B,T,C)

    float* qkv; cudaGetSymbolAddress((void**)&qkv, g_qkv);
    float* att; cudaGetSymbolAddress((void**)&att, g_att);

    const int M = BATCH * TSEQ;   // 4096

    // 1) QKV projection: (4096,1024) @ (1024,3072) + bias
    {
        dim3 grid(QKVN / 128, M / 128);   // (24, 32)
        sgemm_bias_kernel<<<grid, 256>>>(x, w_qkv, b_qkv, qkv, M, QKVN, CDIM);
    }

    // 2) Flash attention -> g_att (B,T,C)
    {
        dim3 grid(TSEQ / 128, NHEADS, BATCH);   // (16, 16, 2)
        flash_attn_kernel<<<grid, 128>>>(qkv, att);
    }

    // 3) Output projection: (4096,1024) @ (1024,1024) + bias
    {
        dim3 grid(CDIM / 128, M / 128);   // (8, 32)
        sgemm_bias_kernel<<<grid, 256>>>(att, w_proj, b_proj, out, M, CDIM, CDIM);
    }
}

// round 5
// speedup vs baseline: 3.4053x; 3.4015x over previous
#include <cuda_runtime.h>
#include <cuda_bf16.h>
#include <cstdint>

// Problem constants
#define BATCH   2
#define TSEQ    2048
#define CDIM    1024
#define NHEADS  16
#define HDIM    64
#define QKVN    (3 * CDIM)  // 3072

// Scratch (allocation-free rule: __device__ globals)
__device__ float g_qkv[(size_t)BATCH * TSEQ * 3 * CDIM];  // (B,T,3C)
__device__ float g_att[(size_t)BATCH * TSEQ * CDIM];      // attention out (B,T,C)

// ---------------------------------------------------------------------------
// Helpers: tf32 rounding + m16n8k8 tf32 mma
// ---------------------------------------------------------------------------
__device__ __forceinline__ float to_tf32(float x) {
    uint32_t u;
    asm("cvt.rna.tf32.f32 %0, %1;" : "=r"(u) : "f"(x));
    return __uint_as_float(u);
}

__device__ __forceinline__ void mma8(float c[4], const float a[4], const float b[2]) {
    asm volatile(
        "mma.sync.aligned.m16n8k8.row.col.f32.tf32.tf32.f32 "
        "{%0,%1,%2,%3}, {%4,%5,%6,%7}, {%8,%9}, {%0,%1,%2,%3};\n"
        : "+f"(c[0]), "+f"(c[1]), "+f"(c[2]), "+f"(c[3])
        : "r"(__float_as_uint(a[0])), "r"(__float_as_uint(a[1])),
          "r"(__float_as_uint(a[2])), "r"(__float_as_uint(a[3])),
          "r"(__float_as_uint(b[0])), "r"(__float_as_uint(b[1])));
}

// ---------------------------------------------------------------------------
// TF32 tensor-core SGEMM:  C[M,N] = A[M,K] @ B[K,N] + bias[N]
// 128x128x16 CTA tile, 8 warps, warp tile 32x64 (2 m-tiles x 8 n-tiles)
// smem padded to stride 136: fragment LDS are bank-conflict-free
// ---------------------------------------------------------------------------
#define GPAD 136

__global__ __launch_bounds__(256) void gemm_tf32_kernel(
    const float* __restrict__ A, const float* __restrict__ B,
    const float* __restrict__ bias, float* __restrict__ C,
    int M, int N, int K)
{
    __shared__ float As[16][GPAD];   // [k][m]
    __shared__ float Bs[16][GPAD];   // [k][n]

    const int tid  = threadIdx.x;
    const int lane = tid & 31;
    const int wid  = tid >> 5;
    const int g    = lane >> 2;     // groupID
    const int tig  = lane & 3;      // thread-in-group
    const int wm   = (wid & 3) * 32;   // warp row base within CTA tile
    const int wn   = (wid >> 2) * 64;  // warp col base within CTA tile

    const int bm = blockIdx.y * 128;
    const int bn = blockIdx.x * 128;

    // loaders
    const int ar  = tid >> 2;            // 0..63
    const int ac4 = (tid & 3) * 4;       // 0,4,8,12
    const int br  = tid >> 5;            // 0..7
    const int bc4 = (tid & 31) * 4;      // 0..124

    float acc[2][8][4];
    #pragma unroll
    for (int mt = 0; mt < 2; mt++)
        #pragma unroll
        for (int nt = 0; nt < 8; nt++)
            #pragma unroll
            for (int i = 0; i < 4; i++) acc[mt][nt][i] = 0.0f;

    for (int k0 = 0; k0 < K; k0 += 16) {
        // prefetch globals
        float4 a0v = *(const float4*)&A[(size_t)(bm + ar) * K + k0 + ac4];
        float4 a1v = *(const float4*)&A[(size_t)(bm + 64 + ar) * K + k0 + ac4];
        float4 b0v = *(const float4*)&B[(size_t)(k0 + br) * N + bn + bc4];
        float4 b1v = *(const float4*)&B[(size_t)(k0 + 8 + br) * N + bn + bc4];
        __syncthreads();
        As[ac4 + 0][ar] = to_tf32(a0v.x);
        As[ac4 + 1][ar] = to_tf32(a0v.y);
        As[ac4 + 2][ar] = to_tf32(a0v.z);
        As[ac4 + 3][ar] = to_tf32(a0v.w);
        As[ac4 + 0][64 + ar] = to_tf32(a1v.x);
        As[ac4 + 1][64 + ar] = to_tf32(a1v.y);
        As[ac4 + 2][64 + ar] = to_tf32(a1v.z);
        As[ac4 + 3][64 + ar] = to_tf32(a1v.w);
        Bs[br][bc4 + 0] = to_tf32(b0v.x);
        Bs[br][bc4 + 1] = to_tf32(b0v.y);
        Bs[br][bc4 + 2] = to_tf32(b0v.z);
        Bs[br][bc4 + 3] = to_tf32(b0v.w);
        Bs[8 + br][bc4 + 0] = to_tf32(b1v.x);
        Bs[8 + br][bc4 + 1] = to_tf32(b1v.y);
        Bs[8 + br][bc4 + 2] = to_tf32(b1v.z);
        Bs[8 + br][bc4 + 3] = to_tf32(b1v.w);
        __syncthreads();

        #pragma unroll
        for (int kk = 0; kk < 16; kk += 8) {
            float af[2][4];
            #pragma unroll
            for (int mt = 0; mt < 2; mt++) {
                const int m0 = wm + mt * 16;
                af[mt][0] = As[kk + tig][m0 + g];
                af[mt][1] = As[kk + tig][m0 + g + 8];
                af[mt][2] = As[kk + tig + 4][m0 + g];
                af[mt][3] = As[kk + tig + 4][m0 + g + 8];
            }
            #pragma unroll
            for (int nt = 0; nt < 8; nt++) {
                const int n0 = wn + nt * 8;
                float bf[2];
                bf[0] = Bs[kk + tig][n0 + g];
                bf[1] = Bs[kk + tig + 4][n0 + g];
                mma8(acc[0][nt], af[0], bf);
                mma8(acc[1][nt], af[1], bf);
            }
        }
    }

    // epilogue: C layout c0:(g,2t) c1:(g,2t+1) c2:(g+8,2t) c3:(g+8,2t+1)
    #pragma unroll
    for (int mt = 0; mt < 2; mt++) {
        const int r0 = bm + wm + mt * 16 + g;
        #pragma unroll
        for (int nt = 0; nt < 8; nt++) {
            const int cc = bn + wn + nt * 8 + 2 * tig;
            const float2 bi = *(const float2*)&bias[cc];
            float2 v0 = { acc[mt][nt][0] + bi.x, acc[mt][nt][1] + bi.y };
            float2 v1 = { acc[mt][nt][2] + bi.x, acc[mt][nt][3] + bi.y };
            *(float2*)&C[(size_t)r0 * N + cc]       = v0;
            *(float2*)&C[(size_t)(r0 + 8) * N + cc] = v1;
        }
    }
}

// ---------------------------------------------------------------------------
// TF32 tensor-core flash attention.
// CTA = (b, h, 64 query rows), 4 warps x 16 rows. K-tile = 64 keys.
// Q fragments register-resident; S and P live in C-fragment registers;
// P(C-layout) -> A-layout via quad shuffles (no smem round trip).
// ---------------------------------------------------------------------------
__global__ __launch_bounds__(128) void flash_mma_kernel(
    const float* __restrict__ qkv, float* __restrict__ out)
{
    __shared__ float ks[64][68];   // keys x dims (tf32), also Q staging
    __shared__ float vs[64][72];   // keys x dims (tf32)

    const int b   = blockIdx.z;
    const int h   = blockIdx.y;
    const int q0  = blockIdx.x * 64;
    const int tid = threadIdx.x;
    const int w    = tid >> 5;
    const int lane = tid & 31;
    const int g    = lane >> 2;
    const int tig  = lane & 3;

    // ---- stage Q (scaled by D^-0.5, tf32-rounded) through ks ----
    for (int i = tid; i < 64 * 16; i += 128) {
        const int row = i >> 4;
        const int c4  = (i & 15) << 2;
        const float4 v = *(const float4*)&qkv[((size_t)(b * TSEQ + q0 + row)) * QKVN + h * HDIM + c4];
        ks[row][c4 + 0] = to_tf32(v.x * 0.125f);
        ks[row][c4 + 1] = to_tf32(v.y * 0.125f);
        ks[row][c4 + 2] = to_tf32(v.z * 0.125f);
        ks[row][c4 + 3] = to_tf32(v.w * 0.125f);
    }
    __syncthreads();

    float qf[8][4];
    {
        const int qr = w * 16;
        #pragma unroll
        for (int kk = 0; kk < 8; kk++) {
            qf[kk][0] = ks[qr + g][kk * 8 + tig];
            qf[kk][1] = ks[qr + g + 8][kk * 8 + tig];
            qf[kk][2] = ks[qr + g][kk * 8 + tig + 4];
            qf[kk][3] = ks[qr + g + 8][kk * 8 + tig + 4];
        }
    }

    float o[8][4];
    #pragma unroll
    for (int nt = 0; nt < 8; nt++)
        #pragma unroll
        for (int i = 0; i < 4; i++) o[nt][i] = 0.0f;
    float m0 = -1e30f, m1 = -1e30f, l0 = 0.0f, l1 = 0.0f;

    for (int kt = 0; kt < TSEQ; kt += 64) {
        __syncthreads();   // prior tile fully consumed (also covers Q staging)
        for (int i = tid; i < 64 * 16; i += 128) {
            const int row = i >> 4;
            const int c4  = (i & 15) << 2;
            const size_t base = ((size_t)(b * TSEQ + kt + row)) * QKVN + h * HDIM + c4;
            const float4 kv = *(const float4*)&qkv[base + CDIM];
            ks[row][c4 + 0] = to_tf32(kv.x);
            ks[row][c4 + 1] = to_tf32(kv.y);
            ks[row][c4 + 2] = to_tf32(kv.z);
            ks[row][c4 + 3] = to_tf32(kv.w);
            const float4 vv = *(const float4*)&qkv[base + 2 * CDIM];
            vs[row][c4 + 0] = to_tf32(vv.x);
            vs[row][c4 + 1] = to_tf32(vv.y);
            vs[row][c4 + 2] = to_tf32(vv.z);
            vs[row][c4 + 3] = to_tf32(vv.w);
        }
        __syncthreads();

        // ---- S = Q @ K^T : 8 n-tiles (keys) x 8 k-steps (dims) ----
        float sv[8][4];
        #pragma unroll
        for (int nt = 0; nt < 8; nt++)
            #pragma unroll
            for (int i = 0; i < 4; i++) sv[nt][i] = 0.0f;

        #pragma unroll
        for (int kk = 0; kk < 8; kk++) {
            #pragma unroll
            for (int nt = 0; nt < 8; nt++) {
                float bf[2];
                bf[0] = ks[nt * 8 + g][kk * 8 + tig];
                bf[1] = ks[nt * 8 + g][kk * 8 + tig + 4];
                mma8(sv[nt], qf[kk], bf);
            }
        }

        // ---- online softmax (rows g and g+8) ----
        float rmax0 = -1e30f, rmax1 = -1e30f;
        #pragma unroll
        for (int nt = 0; nt < 8; nt++) {
            rmax0 = fmaxf(rmax0, fmaxf(sv[nt][0], sv[nt][1]));
            rmax1 = fmaxf(rmax1, fmaxf(sv[nt][2], sv[nt][3]));
        }
        rmax0 = fmaxf(rmax0, __shfl_xor_sync(0xffffffffu, rmax0, 1));
        rmax0 = fmaxf(rmax0, __shfl_xor_sync(0xffffffffu, rmax0, 2));
        rmax1 = fmaxf(rmax1, __shfl_xor_sync(0xffffffffu, rmax1, 1));
        rmax1 = fmaxf(rmax1, __shfl_xor_sync(0xffffffffu, rmax1, 2));

        const float mn0 = fmaxf(m0, rmax0);
        const float mn1 = fmaxf(m1, rmax1);
        const float cr0 = __expf(m0 - mn0);
        const float cr1 = __expf(m1 - mn1);
        m0 = mn0; m1 = mn1;

        float ls0 = 0.0f, ls1 = 0.0f;
        #pragma unroll
        for (int nt = 0; nt < 8; nt++) {
            sv[nt][0] = to_tf32(__expf(sv[nt][0] - mn0)); ls0 += sv[nt][0];
            sv[nt][1] = to_tf32(__expf(sv[nt][1] - mn0)); ls0 += sv[nt][1];
            sv[nt][2] = to_tf32(__expf(sv[nt][2] - mn1)); ls1 += sv[nt][2];
            sv[nt][3] = to_tf32(__expf(sv[nt][3] - mn1)); ls1 += sv[nt][3];
        }
        ls0 += __shfl_xor_sync(0xffffffffu, ls0, 1);
        ls0 += __shfl_xor_sync(0xffffffffu, ls0, 2);
        ls1 += __shfl_xor_sync(0xffffffffu, ls1, 1);
        ls1 += __shfl_xor_sync(0xffffffffu, ls1, 2);
        l0 = l0 * cr0 + ls0;
        l1 = l1 * cr1 + ls1;

        #pragma unroll
        for (int nt = 0; nt < 8; nt++) {
            o[nt][0] *= cr0; o[nt][1] *= cr0;
            o[nt][2] *= cr1; o[nt][3] *= cr1;
        }

        // ---- O += P @ V : P C-layout -> A-layout via quad shuffles ----
        const int srcbase = lane & ~3;
        const bool odd = (tig & 1) != 0;
        #pragma unroll
        for (int kk = 0; kk < 8; kk++) {
            const int s0 = srcbase | (tig >> 1);
            // row g (regs 0/1), row g+8 (regs 2/3); cols tig and tig+4
            const float e00 = __shfl_sync(0xffffffffu, sv[kk][0], s0);
            const float e01 = __shfl_sync(0xffffffffu, sv[kk][1], s0);
            const float e10 = __shfl_sync(0xffffffffu, sv[kk][2], s0);
            const float e11 = __shfl_sync(0xffffffffu, sv[kk][3], s0);
            const float e20 = __shfl_sync(0xffffffffu, sv[kk][0], s0 + 2);
            const float e21 = __shfl_sync(0xffffffffu, sv[kk][1], s0 + 2);
            const float e30 = __shfl_sync(0xffffffffu, sv[kk][2], s0 + 2);
            const float e31 = __shfl_sync(0xffffffffu, sv[kk][3], s0 + 2);
            float af[4];
            af[0] = odd ? e01 : e00;   // (g,     kk*8+tig)
            af[1] = odd ? e11 : e10;   // (g+8,   kk*8+tig)
            af[2] = odd ? e21 : e20;   // (g,     kk*8+tig+4)
            af[3] = odd ? e31 : e30;   // (g+8,   kk*8+tig+4)
            #pragma unroll
            for (int nt = 0; nt < 8; nt++) {
                float bf[2];
                bf[0] = vs[kk * 8 + tig][nt * 8 + g];
                bf[1] = vs[kk * 8 + tig + 4][nt * 8 + g];
                mma8(o[nt], af, bf);
            }
        }
    }

    // ---- epilogue ----
    const float i0 = 1.0f / l0;
    const float i1 = 1.0f / l1;
    const int r0 = q0 + w * 16 + g;
    #pragma unroll
    for (int nt = 0; nt < 8; nt++) {
        const int cc = h * HDIM + nt * 8 + 2 * tig;
        float2 u0 = { o[nt][0] * i0, o[nt][1] * i0 };
        float2 u1 = { o[nt][2] * i1, o[nt][3] * i1 };
        *(float2*)&out[((size_t)(b * TSEQ + r0)) * CDIM + cc]     = u0;
        *(float2*)&out[((size_t)(b * TSEQ + r0 + 8)) * CDIM + cc] = u1;
    }
}

// ---------------------------------------------------------------------------
// Launch
// ---------------------------------------------------------------------------
extern "C" void kernel_launch(void* const* d_in, const int* in_sizes, int n_in,
                              void* d_out, int out_size)
{
    const float* x      = (const float*)d_in[0];
    const float* w_qkv  = (const float*)d_in[1];
    const float* b_qkv  = (const float*)d_in[2];
    const float* w_proj = (const float*)d_in[3];
    const float* b_proj = (const float*)d_in[4];
    float* out = (float*)d_out;

    float* qkv; cudaGetSymbolAddress((void**)&qkv, g_qkv);
    float* att; cudaGetSymbolAddress((void**)&att, g_att);

    const int M = BATCH * TSEQ;   // 4096

    {   // 1) QKV projection: (4096,1024)@(1024,3072)+bias
        dim3 grid(QKVN / 128, M / 128);   // (24, 32)
        gemm_tf32_kernel<<<grid, 256>>>(x, w_qkv, b_qkv, qkv, M, QKVN, CDIM);
    }
    {   // 2) Flash attention (tensor cores)
        dim3 grid(TSEQ / 64, NHEADS, BATCH);   // (32, 16, 2)
        flash_mma_kernel<<<grid, 128>>>(qkv, att);
    }
    {   // 3) Output projection: (4096,1024)@(1024,1024)+bias
        dim3 grid(CDIM / 128, M / 128);   // (8, 32)
        gemm_tf32_kernel<<<grid, 256>>>(att, w_proj, b_proj, out, M, CDIM, CDIM);
    }
}

// round 6
// speedup vs baseline: 4.0581x; 1.1917x over previous
#include <cuda_runtime.h>
#include <cuda_bf16.h>
#include <cstdint>

// Problem constants
#define BATCH   2
#define TSEQ    2048
#define CDIM    1024
#define NHEADS  16
#define HDIM    64
#define QKVN    (3 * CDIM)  // 3072

// Scratch (allocation-free rule: __device__ globals)
__device__ float g_qkv[(size_t)BATCH * TSEQ * 3 * CDIM];  // (B,T,3C), tf32-rounded, Q pre-scaled
__device__ float g_att[(size_t)BATCH * TSEQ * CDIM];      // attention out (B,T,C), fp32

// ---------------------------------------------------------------------------
// Helpers
// ---------------------------------------------------------------------------
__device__ __forceinline__ float to_tf32(float x) {
    uint32_t u;
    asm("cvt.rna.tf32.f32 %0, %1;" : "=r"(u) : "f"(x));
    return __uint_as_float(u);
}

__device__ __forceinline__ void mma8(float c[4], const float a[4], const float b[2]) {
    asm volatile(
        "mma.sync.aligned.m16n8k8.row.col.f32.tf32.tf32.f32 "
        "{%0,%1,%2,%3}, {%4,%5,%6,%7}, {%8,%9}, {%0,%1,%2,%3};\n"
        : "+f"(c[0]), "+f"(c[1]), "+f"(c[2]), "+f"(c[3])
        : "r"(__float_as_uint(a[0])), "r"(__float_as_uint(a[1])),
          "r"(__float_as_uint(a[2])), "r"(__float_as_uint(a[3])),
          "r"(__float_as_uint(b[0])), "r"(__float_as_uint(b[1])));
}

__device__ __forceinline__ void cpa16(uint32_t smaddr, const void* gptr) {
    asm volatile("cp.async.cg.shared.global [%0], [%1], 16;\n"
                 :: "r"(smaddr), "l"(gptr));
}
#define CP_COMMIT() asm volatile("cp.async.commit_group;\n" ::: "memory")
#define CP_WAIT1()  asm volatile("cp.async.wait_group 1;\n" ::: "memory")
#define CP_WAIT0()  asm volatile("cp.async.wait_group 0;\n" ::: "memory")

// ---------------------------------------------------------------------------
// TF32 tensor-core GEMM: C[M,N] = A[M,K] @ B[K,N] + bias[N]
// 128x128x16 CTA tile, 8 warps (warp tile 32x64), DOUBLE-BUFFERED smem,
// register prefetch of next slab issued before compute, ONE sync per slab.
// qkv_mode=1: outputs tf32-rounded, Q columns (<CDIM) pre-scaled by 0.125.
// ---------------------------------------------------------------------------
#define GPAD 136

__global__ __launch_bounds__(256) void gemm_tf32_kernel(
    const float* __restrict__ A, const float* __restrict__ B,
    const float* __restrict__ bias, float* __restrict__ C,
    int M, int N, int K, int qkv_mode)
{
    __shared__ float As[2][16][GPAD];   // [stage][k][m]
    __shared__ float Bs[2][16][GPAD];   // [stage][k][n]

    const int tid  = threadIdx.x;
    const int lane = tid & 31;
    const int wid  = tid >> 5;
    const int g    = lane >> 2;
    const int tig  = lane & 3;
    const int wm   = (wid & 3) * 32;
    const int wn   = (wid >> 2) * 64;

    const int bm = blockIdx.y * 128;
    const int bn = blockIdx.x * 128;

    const int ar  = tid >> 2;        // 0..63
    const int ac4 = (tid & 3) * 4;   // 0,4,8,12
    const int br  = tid >> 5;        // 0..7
    const int bc4 = (tid & 31) * 4;  // 0..124

    float acc[2][8][4];
    #pragma unroll
    for (int mt = 0; mt < 2; mt++)
        #pragma unroll
        for (int nt = 0; nt < 8; nt++)
            #pragma unroll
            for (int i = 0; i < 4; i++) acc[mt][nt][i] = 0.0f;

    float4 a0v, a1v, b0v, b1v;

    // ---- load slab k0=0 into regs, store into stage 0 ----
    a0v = *(const float4*)&A[(size_t)(bm + ar) * K + ac4];
    a1v = *(const float4*)&A[(size_t)(bm + 64 + ar) * K + ac4];
    b0v = *(const float4*)&B[(size_t)br * N + bn + bc4];
    b1v = *(const float4*)&B[(size_t)(8 + br) * N + bn + bc4];

    #define STORE_STAGE(s)                                                     \
        do {                                                                   \
            As[s][ac4 + 0][ar] = to_tf32(a0v.x);                               \
            As[s][ac4 + 1][ar] = to_tf32(a0v.y);                               \
            As[s][ac4 + 2][ar] = to_tf32(a0v.z);                               \
            As[s][ac4 + 3][ar] = to_tf32(a0v.w);                               \
            As[s][ac4 + 0][64 + ar] = to_tf32(a1v.x);                          \
            As[s][ac4 + 1][64 + ar] = to_tf32(a1v.y);                          \
            As[s][ac4 + 2][64 + ar] = to_tf32(a1v.z);                          \
            As[s][ac4 + 3][64 + ar] = to_tf32(a1v.w);                          \
            Bs[s][br][bc4 + 0] = to_tf32(b0v.x);                               \
            Bs[s][br][bc4 + 1] = to_tf32(b0v.y);                               \
            Bs[s][br][bc4 + 2] = to_tf32(b0v.z);                               \
            Bs[s][br][bc4 + 3] = to_tf32(b0v.w);                               \
            Bs[s][8 + br][bc4 + 0] = to_tf32(b1v.x);                           \
            Bs[s][8 + br][bc4 + 1] = to_tf32(b1v.y);                           \
            Bs[s][8 + br][bc4 + 2] = to_tf32(b1v.z);                           \
            Bs[s][8 + br][bc4 + 3] = to_tf32(b1v.w);                           \
        } while (0)

    STORE_STAGE(0);
    __syncthreads();

    int cur = 0;
    for (int k0 = 0; k0 < K; k0 += 16) {
        const int nk = k0 + 16;
        if (nk < K) {   // prefetch next slab (LDG latency hidden by compute)
            a0v = *(const float4*)&A[(size_t)(bm + ar) * K + nk + ac4];
            a1v = *(const float4*)&A[(size_t)(bm + 64 + ar) * K + nk + ac4];
            b0v = *(const float4*)&B[(size_t)(nk + br) * N + bn + bc4];
            b1v = *(const float4*)&B[(size_t)(nk + 8 + br) * N + bn + bc4];
        }

        #pragma unroll
        for (int kk = 0; kk < 16; kk += 8) {
            float af[2][4];
            #pragma unroll
            for (int mt = 0; mt < 2; mt++) {
                const int m0 = wm + mt * 16;
                af[mt][0] = As[cur][kk + tig][m0 + g];
                af[mt][1] = As[cur][kk + tig][m0 + g + 8];
                af[mt][2] = As[cur][kk + tig + 4][m0 + g];
                af[mt][3] = As[cur][kk + tig + 4][m0 + g + 8];
            }
            #pragma unroll
            for (int nt = 0; nt < 8; nt++) {
                const int n0 = wn + nt * 8;
                float bf[2];
                bf[0] = Bs[cur][kk + tig][n0 + g];
                bf[1] = Bs[cur][kk + tig + 4][n0 + g];
                mma8(acc[0][nt], af[0], bf);
                mma8(acc[1][nt], af[1], bf);
            }
        }

        if (nk < K) STORE_STAGE(cur ^ 1);
        __syncthreads();
        cur ^= 1;
    }
    #undef STORE_STAGE

    // ---- epilogue ----
    #pragma unroll
    for (int mt = 0; mt < 2; mt++) {
        const int r0 = bm + wm + mt * 16 + g;
        #pragma unroll
        for (int nt = 0; nt < 8; nt++) {
            const int cc = bn + wn + nt * 8 + 2 * tig;
            const float2 bi = *(const float2*)&bias[cc];
            float v00 = acc[mt][nt][0] + bi.x, v01 = acc[mt][nt][1] + bi.y;
            float v10 = acc[mt][nt][2] + bi.x, v11 = acc[mt][nt][3] + bi.y;
            if (qkv_mode) {
                const float s = (cc < CDIM) ? 0.125f : 1.0f;  // Q pre-scale
                v00 = to_tf32(v00 * s); v01 = to_tf32(v01 * s);
                v10 = to_tf32(v10 * s); v11 = to_tf32(v11 * s);
            }
            float2 u0 = { v00, v01 }, u1 = { v10, v11 };
            *(float2*)&C[(size_t)r0 * N + cc]       = u0;
            *(float2*)&C[(size_t)(r0 + 8) * N + cc] = u1;
        }
    }
}

// ---------------------------------------------------------------------------
// TF32 tensor-core flash attention, cp.async double-buffered K/V pipeline.
// CTA = (b, h, 64 query rows), 4 warps x 16 rows. K-tile = 64 keys.
// Inputs in g_qkv are already tf32-rounded (Q pre-scaled) by the QKV GEMM.
// ---------------------------------------------------------------------------
#define KSS 68                      // ks row stride (floats)
#define VSS 72                      // vs row stride (floats)
#define FBUF (64 * KSS + 64 * VSS)  // floats per stage: 8960
#define NKT  (TSEQ / 64)            // 32 key tiles

__global__ __launch_bounds__(128) void flash_mma_kernel(
    const float* __restrict__ qkv, float* __restrict__ out)
{
    extern __shared__ float fsm[];  // 2 * FBUF floats = 71680 B

    const int b   = blockIdx.z;
    const int h   = blockIdx.y;
    const int q0  = blockIdx.x * 64;
    const int tid = threadIdx.x;
    const int w    = tid >> 5;
    const int lane = tid & 31;
    const int g    = lane >> 2;
    const int tig  = lane & 3;

    // ---- stage Q through buf1's ks region (values already tf32 + scaled) ----
    {
        float* qs = fsm + FBUF;
        for (int i = tid; i < 64 * 16; i += 128) {
            const int row = i >> 4;
            const int c4  = (i & 15) << 2;
            *(float4*)&qs[row * KSS + c4] =
                *(const float4*)&qkv[((size_t)(b * TSEQ + q0 + row)) * QKVN + h * HDIM + c4];
        }
    }
    __syncthreads();

    float qf[8][4];
    {
        const float* qs = fsm + FBUF;
        const int qr = w * 16;
        #pragma unroll
        for (int kk = 0; kk < 8; kk++) {
            qf[kk][0] = qs[(qr + g) * KSS + kk * 8 + tig];
            qf[kk][1] = qs[(qr + g + 8) * KSS + kk * 8 + tig];
            qf[kk][2] = qs[(qr + g) * KSS + kk * 8 + tig + 4];
            qf[kk][3] = qs[(qr + g + 8) * KSS + kk * 8 + tig + 4];
        }
    }
    __syncthreads();

    float o[8][4];
    #pragma unroll
    for (int nt = 0; nt < 8; nt++)
        #pragma unroll
        for (int i = 0; i < 4; i++) o[nt][i] = 0.0f;
    float m0 = -1e30f, m1 = -1e30f, l0 = 0.0f, l1 = 0.0f;

    // ---- stage tile 0 into buf0 via cp.async ----
    #define STAGE_KV(buf_idx, kt)                                              \
        do {                                                                   \
            float* ksb = fsm + (buf_idx) * FBUF;                               \
            float* vsb = ksb + 64 * KSS;                                       \
            for (int i = tid; i < 64 * 16; i += 128) {                         \
                const int row = i >> 4;                                        \
                const int c4  = (i & 15) << 2;                                 \
                const size_t base =                                            \
                    ((size_t)(b * TSEQ + (kt) + row)) * QKVN + h * HDIM + c4;  \
                cpa16((uint32_t)__cvta_generic_to_shared(&ksb[row * KSS + c4]),\
                      &qkv[base + CDIM]);                                      \
                cpa16((uint32_t)__cvta_generic_to_shared(&vsb[row * VSS + c4]),\
                      &qkv[base + 2 * CDIM]);                                  \
            }                                                                  \
        } while (0)

    STAGE_KV(0, 0);
    CP_COMMIT();

    for (int it = 0; it < NKT; it++) {
        if (it + 1 < NKT) {
            STAGE_KV((it + 1) & 1, (it + 1) * 64);
            CP_COMMIT();
            CP_WAIT1();   // current tile complete; next may be in flight
        } else {
            CP_WAIT0();
        }
        __syncthreads();

        const float* ks = fsm + (it & 1) * FBUF;
        const float* vs = ks + 64 * KSS;

        // ---- S = Q @ K^T ----
        float sv[8][4];
        #pragma unroll
        for (int nt = 0; nt < 8; nt++)
            #pragma unroll
            for (int i = 0; i < 4; i++) sv[nt][i] = 0.0f;

        #pragma unroll
        for (int kk = 0; kk < 8; kk++) {
            #pragma unroll
            for (int nt = 0; nt < 8; nt++) {
                float bf[2];
                bf[0] = ks[(nt * 8 + g) * KSS + kk * 8 + tig];
                bf[1] = ks[(nt * 8 + g) * KSS + kk * 8 + tig + 4];
                mma8(sv[nt], qf[kk], bf);
            }
        }

        // ---- online softmax (rows g and g+8) ----
        float rmax0 = -1e30f, rmax1 = -1e30f;
        #pragma unroll
        for (int nt = 0; nt < 8; nt++) {
            rmax0 = fmaxf(rmax0, fmaxf(sv[nt][0], sv[nt][1]));
            rmax1 = fmaxf(rmax1, fmaxf(sv[nt][2], sv[nt][3]));
        }
        rmax0 = fmaxf(rmax0, __shfl_xor_sync(0xffffffffu, rmax0, 1));
        rmax0 = fmaxf(rmax0, __shfl_xor_sync(0xffffffffu, rmax0, 2));
        rmax1 = fmaxf(rmax1, __shfl_xor_sync(0xffffffffu, rmax1, 1));
        rmax1 = fmaxf(rmax1, __shfl_xor_sync(0xffffffffu, rmax1, 2));

        const float mn0 = fmaxf(m0, rmax0);
        const float mn1 = fmaxf(m1, rmax1);
        const float cr0 = __expf(m0 - mn0);
        const float cr1 = __expf(m1 - mn1);
        m0 = mn0; m1 = mn1;

        float ls0 = 0.0f, ls1 = 0.0f;
        #pragma unroll
        for (int nt = 0; nt < 8; nt++) {
            sv[nt][0] = to_tf32(__expf(sv[nt][0] - mn0)); ls0 += sv[nt][0];
            sv[nt][1] = to_tf32(__expf(sv[nt][1] - mn0)); ls0 += sv[nt][1];
            sv[nt][2] = to_tf32(__expf(sv[nt][2] - mn1)); ls1 += sv[nt][2];
            sv[nt][3] = to_tf32(__expf(sv[nt][3] - mn1)); ls1 += sv[nt][3];
        }
        ls0 += __shfl_xor_sync(0xffffffffu, ls0, 1);
        ls0 += __shfl_xor_sync(0xffffffffu, ls0, 2);
        ls1 += __shfl_xor_sync(0xffffffffu, ls1, 1);
        ls1 += __shfl_xor_sync(0xffffffffu, ls1, 2);
        l0 = l0 * cr0 + ls0;
        l1 = l1 * cr1 + ls1;

        #pragma unroll
        for (int nt = 0; nt < 8; nt++) {
            o[nt][0] *= cr0; o[nt][1] *= cr0;
            o[nt][2] *= cr1; o[nt][3] *= cr1;
        }

        // ---- O += P @ V : P C-layout -> A-layout via quad shuffles ----
        const int srcbase = lane & ~3;
        const bool odd = (tig & 1) != 0;
        #pragma unroll
        for (int kk = 0; kk < 8; kk++) {
            const int s0 = srcbase | (tig >> 1);
            const float e00 = __shfl_sync(0xffffffffu, sv[kk][0], s0);
            const float e01 = __shfl_sync(0xffffffffu, sv[kk][1], s0);
            const float e10 = __shfl_sync(0xffffffffu, sv[kk][2], s0);
            const float e11 = __shfl_sync(0xffffffffu, sv[kk][3], s0);
            const float e20 = __shfl_sync(0xffffffffu, sv[kk][0], s0 + 2);
            const float e21 = __shfl_sync(0xffffffffu, sv[kk][1], s0 + 2);
            const float e30 = __shfl_sync(0xffffffffu, sv[kk][2], s0 + 2);
            const float e31 = __shfl_sync(0xffffffffu, sv[kk][3], s0 + 2);
            float af[4];
            af[0] = odd ? e01 : e00;
            af[1] = odd ? e11 : e10;
            af[2] = odd ? e21 : e20;
            af[3] = odd ? e31 : e30;
            #pragma unroll
            for (int nt = 0; nt < 8; nt++) {
                float bf[2];
                bf[0] = vs[(kk * 8 + tig) * VSS + nt * 8 + g];
                bf[1] = vs[(kk * 8 + tig + 4) * VSS + nt * 8 + g];
                mma8(o[nt], af, bf);
            }
        }
        __syncthreads();   // tile consumed; its buffer may be re-staged
    }
    #undef STAGE_KV

    // ---- epilogue ----
    const float i0 = 1.0f / l0;
    const float i1 = 1.0f / l1;
    const int r0 = q0 + w * 16 + g;
    #pragma unroll
    for (int nt = 0; nt < 8; nt++) {
        const int cc = h * HDIM + nt * 8 + 2 * tig;
        float2 u0 = { o[nt][0] * i0, o[nt][1] * i0 };
        float2 u1 = { o[nt][2] * i1, o[nt][3] * i1 };
        *(float2*)&out[((size_t)(b * TSEQ + r0)) * CDIM + cc]     = u0;
        *(float2*)&out[((size_t)(b * TSEQ + r0 + 8)) * CDIM + cc] = u1;
    }
}

// ---------------------------------------------------------------------------
// Launch
// ---------------------------------------------------------------------------
extern "C" void kernel_launch(void* const* d_in, const int* in_sizes, int n_in,
                              void* d_out, int out_size)
{
    const float* x      = (const float*)d_in[0];
    const float* w_qkv  = (const float*)d_in[1];
    const float* b_qkv  = (const float*)d_in[2];
    const float* w_proj = (const float*)d_in[3];
    const float* b_proj = (const float*)d_in[4];
    float* out = (float*)d_out;

    float* qkv; cudaGetSymbolAddress((void**)&qkv, g_qkv);
    float* att; cudaGetSymbolAddress((void**)&att, g_att);

    const int M = BATCH * TSEQ;          // 4096
    const int FLASH_SMEM = 2 * FBUF * 4; // 71680 B

    static int attr_done = 0;
    if (!attr_done) {
        cudaFuncSetAttribute(flash_mma_kernel,
                             cudaFuncAttributeMaxDynamicSharedMemorySize, FLASH_SMEM);
        attr_done = 1;
    }

    {   // 1) QKV projection (+ tf32 rounding, Q pre-scale in epilogue)
        dim3 grid(QKVN / 128, M / 128);   // (24, 32)
        gemm_tf32_kernel<<<grid, 256>>>(x, w_qkv, b_qkv, qkv, M, QKVN, CDIM, 1);
    }
    {   // 2) Flash attention (tensor cores, cp.async double buffer)
        dim3 grid(TSEQ / 64, NHEADS, BATCH);   // (32, 16, 2)
        flash_mma_kernel<<<grid, 128, FLASH_SMEM>>>(qkv, att);
    }
    {   // 3) Output projection
        dim3 grid(CDIM / 128, M / 128);   // (8, 32)
        gemm_tf32_kernel<<<grid, 256>>>(att, w_proj, b_proj, out, M, CDIM, CDIM, 0);
    }
}

// round 7
// speedup vs baseline: 4.3849x; 1.0805x over previous
#include <cuda_runtime.h>
#include <cuda_bf16.h>
#include <cstdint>

// Problem constants
#define BATCH   2
#define TSEQ    2048
#define CDIM    1024
#define NHEADS  16
#define HDIM    64
#define QKVN    (3 * CDIM)  // 3072

// Scratch (allocation-free rule: __device__ globals)
__device__ float g_qkv[(size_t)BATCH * TSEQ * 3 * CDIM];   // (B,T,3C), tf32, Q pre-scaled
__device__ float g_att[(size_t)BATCH * TSEQ * CDIM];       // attn out, tf32-rounded
__device__ float g_xt[(size_t)BATCH * TSEQ * CDIM];        // x, tf32
__device__ float g_wqkv_t[(size_t)CDIM * QKVN];            // w_qkv, tf32
__device__ float g_wproj_t[(size_t)CDIM * CDIM];           // w_proj, tf32

// ---------------------------------------------------------------------------
// Helpers
// ---------------------------------------------------------------------------
__device__ __forceinline__ float to_tf32(float x) {
    uint32_t u;
    asm("cvt.rna.tf32.f32 %0, %1;" : "=r"(u) : "f"(x));
    return __uint_as_float(u);
}

__device__ __forceinline__ void mma8(float c[4], const float a[4], const float b[2]) {
    asm volatile(
        "mma.sync.aligned.m16n8k8.row.col.f32.tf32.tf32.f32 "
        "{%0,%1,%2,%3}, {%4,%5,%6,%7}, {%8,%9}, {%0,%1,%2,%3};\n"
        : "+f"(c[0]), "+f"(c[1]), "+f"(c[2]), "+f"(c[3])
        : "r"(__float_as_uint(a[0])), "r"(__float_as_uint(a[1])),
          "r"(__float_as_uint(a[2])), "r"(__float_as_uint(a[3])),
          "r"(__float_as_uint(b[0])), "r"(__float_as_uint(b[1])));
}

__device__ __forceinline__ void mma8u(float c[4], const uint32_t a[4], const float b[2]) {
    asm volatile(
        "mma.sync.aligned.m16n8k8.row.col.f32.tf32.tf32.f32 "
        "{%0,%1,%2,%3}, {%4,%5,%6,%7}, {%8,%9}, {%0,%1,%2,%3};\n"
        : "+f"(c[0]), "+f"(c[1]), "+f"(c[2]), "+f"(c[3])
        : "r"(a[0]), "r"(a[1]), "r"(a[2]), "r"(a[3]),
          "r"(__float_as_uint(b[0])), "r"(__float_as_uint(b[1])));
}

__device__ __forceinline__ void ldsm4(uint32_t r[4], uint32_t a) {
    asm volatile("ldmatrix.sync.aligned.m8n8.x4.shared.b16 {%0,%1,%2,%3}, [%4];"
                 : "=r"(r[0]), "=r"(r[1]), "=r"(r[2]), "=r"(r[3]) : "r"(a));
}

__device__ __forceinline__ void cpa16(uint32_t smaddr, const void* gptr) {
    asm volatile("cp.async.cg.shared.global [%0], [%1], 16;\n"
                 :: "r"(smaddr), "l"(gptr));
}
#define CP_COMMIT() asm volatile("cp.async.commit_group;\n" ::: "memory")
#define CP_WAITG(n) asm volatile("cp.async.wait_group %0;\n" :: "n"(n) : "memory")

// ---------------------------------------------------------------------------
// Pre-pass: RNA tf32 conversion (elementwise, float4)
// ---------------------------------------------------------------------------
__global__ __launch_bounds__(256) void tf32_convert_kernel(
    const float* __restrict__ in, float* __restrict__ out, int n4)
{
    const int i = blockIdx.x * blockDim.x + threadIdx.x;
    if (i < n4) {
        float4 v = ((const float4*)in)[i];
        v.x = to_tf32(v.x); v.y = to_tf32(v.y);
        v.z = to_tf32(v.z); v.w = to_tf32(v.w);
        ((float4*)out)[i] = v;
    }
}

// ---------------------------------------------------------------------------
// TF32 tensor-core GEMM (inputs pre-converted to tf32):
//   C[M,N] = A[M,K] @ B[K,N] + bias[N]
// 128x128x16 CTA tile, 8 warps (warp tile 32x64).
// 3-stage cp.async pipeline; A in [m][k] layout (stride 20) for ldmatrix.x4;
// B in [k][n] layout (stride 136), scalar LDS conflict-free.
// qkv_mode=1: outputs tf32-rounded, first CDIM cols (Q) pre-scaled by 0.125.
// ---------------------------------------------------------------------------
#define ASTRIDE 20
#define ASZ  (128 * ASTRIDE)        // 2560 floats
#define BSTRIDE 136
#define BSZ  (16 * BSTRIDE)         // 2176 floats
#define STGF (ASZ + BSZ)            // 4736 floats/stage
#define GEMM_SMEM (3 * STGF * 4)    // 56832 bytes

__global__ __launch_bounds__(256, 2) void gemm_tf32_kernel(
    const float* __restrict__ A, const float* __restrict__ B,
    const float* __restrict__ bias, float* __restrict__ C,
    int M, int N, int K, int qkv_mode)
{
    extern __shared__ float sm[];
    const uint32_t smb = (uint32_t)__cvta_generic_to_shared(sm);

    const int tid  = threadIdx.x;
    const int lane = tid & 31;
    const int wid  = tid >> 5;
    const int g    = lane >> 2;
    const int tig  = lane & 3;
    const int wm   = (wid & 3) * 32;
    const int wn   = (wid >> 2) * 64;

    const int bm = blockIdx.y * 128;
    const int bn = blockIdx.x * 128;

    // ldmatrix per-lane source row/col
    const int lrow = lane & 15;            // row within 16-row pair block
    const int lk4  = (lane >> 4) << 2;     // 0 or 4 (k offset)
    // byte address of this lane's ldmatrix row, relative to stage base, mt=0, kk=0
    const uint32_t a_lane_off = (uint32_t)(((wm + lrow) * ASTRIDE + lk4) * 4);

    float acc[2][8][4];
    #pragma unroll
    for (int mt = 0; mt < 2; mt++)
        #pragma unroll
        for (int nt = 0; nt < 8; nt++)
            #pragma unroll
            for (int i = 0; i < 4; i++) acc[mt][nt][i] = 0.0f;

    // ---- cp.async stage issue: A 512 chunks (m=c>>2, kc=(c&3)*4),
    //                            B 512 chunks (k=c>>5, nc=(c&31)*4)
    #define ISSUE(s, k0)                                                        \
        do {                                                                    \
            const uint32_t sb = smb + (uint32_t)((s) * STGF * 4);               \
            _Pragma("unroll")                                                   \
            for (int c = tid; c < 512; c += 256) {                              \
                const int m_ = c >> 2, kc_ = (c & 3) << 2;                      \
                cpa16(sb + (uint32_t)((m_ * ASTRIDE + kc_) * 4),                \
                      &A[(size_t)(bm + m_) * K + (k0) + kc_]);                  \
            }                                                                   \
            _Pragma("unroll")                                                   \
            for (int c = tid; c < 512; c += 256) {                              \
                const int k_ = c >> 5, nc_ = (c & 31) << 2;                     \
                cpa16(sb + (uint32_t)((ASZ + k_ * BSTRIDE + nc_) * 4),          \
                      &B[(size_t)((k0) + k_) * N + bn + nc_]);                  \
            }                                                                   \
        } while (0)

    const int ns = K / 16;
    ISSUE(0, 0);  CP_COMMIT();
    ISSUE(1, 16); CP_COMMIT();

    int cur = 0;
    for (int i = 0; i < ns; i++) {
        CP_WAITG(1);        // oldest pending group (stage i) complete
        __syncthreads();    // data visible to all; all threads done with stage i-1

        if (i + 2 < ns) {
            const int s2 = (cur + 2 >= 3) ? cur - 1 : cur + 2;
            ISSUE(s2, (i + 2) * 16);
        }
        CP_COMMIT();        // always commit (possibly empty) to keep group math fixed

        const float* bs = sm + cur * STGF + ASZ;
        const uint32_t ab = smb + (uint32_t)(cur * STGF * 4) + a_lane_off;

        #pragma unroll
        for (int kk = 0; kk < 16; kk += 8) {
            uint32_t af[2][4];
            ldsm4(af[0], ab + (uint32_t)(kk * 4));
            ldsm4(af[1], ab + (uint32_t)((16 * ASTRIDE + kk) * 4));
            #pragma unroll
            for (int nt = 0; nt < 8; nt++) {
                const int n0 = wn + nt * 8;
                float bf[2];
                bf[0] = bs[(kk + tig) * BSTRIDE + n0 + g];
                bf[1] = bs[(kk + tig + 4) * BSTRIDE + n0 + g];
                mma8u(acc[0][nt], af[0], bf);
                mma8u(acc[1][nt], af[1], bf);
            }
        }
        cur = (cur + 1 == 3) ? 0 : cur + 1;
    }
    #undef ISSUE

    // ---- epilogue ----
    #pragma unroll
    for (int mt = 0; mt < 2; mt++) {
        const int r0 = bm + wm + mt * 16 + g;
        #pragma unroll
        for (int nt = 0; nt < 8; nt++) {
            const int cc = bn + wn + nt * 8 + 2 * tig;
            const float2 bi = *(const float2*)&bias[cc];
            float v00 = acc[mt][nt][0] + bi.x, v01 = acc[mt][nt][1] + bi.y;
            float v10 = acc[mt][nt][2] + bi.x, v11 = acc[mt][nt][3] + bi.y;
            if (qkv_mode) {
                const float s = (cc < CDIM) ? 0.125f : 1.0f;   // Q pre-scale
                v00 = to_tf32(v00 * s); v01 = to_tf32(v01 * s);
                v10 = to_tf32(v10 * s); v11 = to_tf32(v11 * s);
            }
            float2 u0 = { v00, v01 }, u1 = { v10, v11 };
            *(float2*)&C[(size_t)r0 * N + cc]       = u0;
            *(float2*)&C[(size_t)(r0 + 8) * N + cc] = u1;
        }
    }
}

// ---------------------------------------------------------------------------
// TF32 tensor-core flash attention, cp.async double-buffered K/V pipeline.
// CTA = (b, h, 64 query rows), 4 warps x 16 rows. K-tile = 64 keys.
// Inputs in g_qkv already tf32 (Q pre-scaled). Output tf32-rounded for proj.
// ---------------------------------------------------------------------------
#define KSS 68
#define VSS 72
#define FBUF (64 * KSS + 64 * VSS)  // 8960 floats/stage
#define NKT  (TSEQ / 64)
#define FLASH_SMEM (2 * FBUF * 4)   // 71680 B

__global__ __launch_bounds__(128) void flash_mma_kernel(
    const float* __restrict__ qkv, float* __restrict__ out)
{
    extern __shared__ float fsm[];

    const int b   = blockIdx.z;
    const int h   = blockIdx.y;
    const int q0  = blockIdx.x * 64;
    const int tid = threadIdx.x;
    const int w    = tid >> 5;
    const int lane = tid & 31;
    const int g    = lane >> 2;
    const int tig  = lane & 3;

    // ---- stage Q through buf1's ks region ----
    {
        float* qs = fsm + FBUF;
        for (int i = tid; i < 64 * 16; i += 128) {
            const int row = i >> 4;
            const int c4  = (i & 15) << 2;
            *(float4*)&qs[row * KSS + c4] =
                *(const float4*)&qkv[((size_t)(b * TSEQ + q0 + row)) * QKVN + h * HDIM + c4];
        }
    }
    __syncthreads();

    float qf[8][4];
    {
        const float* qs = fsm + FBUF;
        const int qr = w * 16;
        #pragma unroll
        for (int kk = 0; kk < 8; kk++) {
            qf[kk][0] = qs[(qr + g) * KSS + kk * 8 + tig];
            qf[kk][1] = qs[(qr + g + 8) * KSS + kk * 8 + tig];
            qf[kk][2] = qs[(qr + g) * KSS + kk * 8 + tig + 4];
            qf[kk][3] = qs[(qr + g + 8) * KSS + kk * 8 + tig + 4];
        }
    }
    __syncthreads();

    float o[8][4];
    #pragma unroll
    for (int nt = 0; nt < 8; nt++)
        #pragma unroll
        for (int i = 0; i < 4; i++) o[nt][i] = 0.0f;
    float m0 = -1e30f, m1 = -1e30f, l0 = 0.0f, l1 = 0.0f;

    #define STAGE_KV(buf_idx, kt)                                              \
        do {                                                                   \
            float* ksb = fsm + (buf_idx) * FBUF;                               \
            float* vsb = ksb + 64 * KSS;                                       \
            for (int i = tid; i < 64 * 16; i += 128) {                         \
                const int row = i >> 4;                                        \
                const int c4  = (i & 15) << 2;                                 \
                const size_t base =                                            \
                    ((size_t)(b * TSEQ + (kt) + row)) * QKVN + h * HDIM + c4;  \
                cpa16((uint32_t)__cvta_generic_to_shared(&ksb[row * KSS + c4]),\
                      &qkv[base + CDIM]);                                      \
                cpa16((uint32_t)__cvta_generic_to_shared(&vsb[row * VSS + c4]),\
                      &qkv[base + 2 * CDIM]);                                  \
            }                                                                  \
        } while (0)

    STAGE_KV(0, 0);
    CP_COMMIT();

    for (int it = 0; it < NKT; it++) {
        if (it + 1 < NKT) {
            STAGE_KV((it + 1) & 1, (it + 1) * 64);
            CP_COMMIT();
            CP_WAITG(1);
        } else {
            CP_WAITG(0);
        }
        __syncthreads();

        const float* ks = fsm + (it & 1) * FBUF;
        const float* vs = ks + 64 * KSS;

        // ---- S = Q @ K^T ----
        float sv[8][4];
        #pragma unroll
        for (int nt = 0; nt < 8; nt++)
            #pragma unroll
            for (int i = 0; i < 4; i++) sv[nt][i] = 0.0f;

        #pragma unroll
        for (int kk = 0; kk < 8; kk++) {
            #pragma unroll
            for (int nt = 0; nt < 8; nt++) {
                float bf[2];
                bf[0] = ks[(nt * 8 + g) * KSS + kk * 8 + tig];
                bf[1] = ks[(nt * 8 + g) * KSS + kk * 8 + tig + 4];
                mma8(sv[nt], qf[kk], bf);
            }
        }

        // ---- online softmax (rows g and g+8) ----
        float rmax0 = -1e30f, rmax1 = -1e30f;
        #pragma unroll
        for (int nt = 0; nt < 8; nt++) {
            rmax0 = fmaxf(rmax0, fmaxf(sv[nt][0], sv[nt][1]));
            rmax1 = fmaxf(rmax1, fmaxf(sv[nt][2], sv[nt][3]));
        }
        rmax0 = fmaxf(rmax0, __shfl_xor_sync(0xffffffffu, rmax0, 1));
        rmax0 = fmaxf(rmax0, __shfl_xor_sync(0xffffffffu, rmax0, 2));
        rmax1 = fmaxf(rmax1, __shfl_xor_sync(0xffffffffu, rmax1, 1));
        rmax1 = fmaxf(rmax1, __shfl_xor_sync(0xffffffffu, rmax1, 2));

        const float mn0 = fmaxf(m0, rmax0);
        const float mn1 = fmaxf(m1, rmax1);
        const float cr0 = __expf(m0 - mn0);
        const float cr1 = __expf(m1 - mn1);
        m0 = mn0; m1 = mn1;

        float ls0 = 0.0f, ls1 = 0.0f;
        #pragma unroll
        for (int nt = 0; nt < 8; nt++) {
            sv[nt][0] = to_tf32(__expf(sv[nt][0] - mn0)); ls0 += sv[nt][0];
            sv[nt][1] = to_tf32(__expf(sv[nt][1] - mn0)); ls0 += sv[nt][1];
            sv[nt][2] = to_tf32(__expf(sv[nt][2] - mn1)); ls1 += sv[nt][2];
            sv[nt][3] = to_tf32(__expf(sv[nt][3] - mn1)); ls1 += sv[nt][3];
        }
        ls0 += __shfl_xor_sync(0xffffffffu, ls0, 1);
        ls0 += __shfl_xor_sync(0xffffffffu, ls0, 2);
        ls1 += __shfl_xor_sync(0xffffffffu, ls1, 1);
        ls1 += __shfl_xor_sync(0xffffffffu, ls1, 2);
        l0 = l0 * cr0 + ls0;
        l1 = l1 * cr1 + ls1;

        #pragma unroll
        for (int nt = 0; nt < 8; nt++) {
            o[nt][0] *= cr0; o[nt][1] *= cr0;
            o[nt][2] *= cr1; o[nt][3] *= cr1;
        }

        // ---- O += P @ V : P C-layout -> A-layout via quad shuffles ----
        const int srcbase = lane & ~3;
        const bool odd = (tig & 1) != 0;
        #pragma unroll
        for (int kk = 0; kk < 8; kk++) {
            const int s0 = srcbase | (tig >> 1);
            const float e00 = __shfl_sync(0xffffffffu, sv[kk][0], s0);
            const float e01 = __shfl_sync(0xffffffffu, sv[kk][1], s0);
            const float e10 = __shfl_sync(0xffffffffu, sv[kk][2], s0);
            const float e11 = __shfl_sync(0xffffffffu, sv[kk][3], s0);
            const float e20 = __shfl_sync(0xffffffffu, sv[kk][0], s0 + 2);
            const float e21 = __shfl_sync(0xffffffffu, sv[kk][1], s0 + 2);
            const float e30 = __shfl_sync(0xffffffffu, sv[kk][2], s0 + 2);
            const float e31 = __shfl_sync(0xffffffffu, sv[kk][3], s0 + 2);
            float af[4];
            af[0] = odd ? e01 : e00;
            af[1] = odd ? e11 : e10;
            af[2] = odd ? e21 : e20;
            af[3] = odd ? e31 : e30;
            #pragma unroll
            for (int nt = 0; nt < 8; nt++) {
                float bf[2];
                bf[0] = vs[(kk * 8 + tig) * VSS + nt * 8 + g];
                bf[1] = vs[(kk * 8 + tig + 4) * VSS + nt * 8 + g];
                mma8(o[nt], af, bf);
            }
        }
        __syncthreads();
    }
    #undef STAGE_KV

    // ---- epilogue: tf32-rounded so proj GEMM needs no conversion ----
    const float i0 = 1.0f / l0;
    const float i1 = 1.0f / l1;
    const int r0 = q0 + w * 16 + g;
    #pragma unroll
    for (int nt = 0; nt < 8; nt++) {
        const int cc = h * HDIM + nt * 8 + 2 * tig;
        float2 u0 = { to_tf32(o[nt][0] * i0), to_tf32(o[nt][1] * i0) };
        float2 u1 = { to_tf32(o[nt][2] * i1), to_tf32(o[nt][3] * i1) };
        *(float2*)&out[((size_t)(b * TSEQ + r0)) * CDIM + cc]     = u0;
        *(float2*)&out[((size_t)(b * TSEQ + r0 + 8)) * CDIM + cc] = u1;
    }
}

// ---------------------------------------------------------------------------
// Launch
// ---------------------------------------------------------------------------
extern "C" void kernel_launch(void* const* d_in, const int* in_sizes, int n_in,
                              void* d_out, int out_size)
{
    const float* x      = (const float*)d_in[0];
    const float* w_qkv  = (const float*)d_in[1];
    const float* b_qkv  = (const float*)d_in[2];
    const float* w_proj = (const float*)d_in[3];
    const float* b_proj = (const float*)d_in[4];
    float* out = (float*)d_out;

    float* qkv;   cudaGetSymbolAddress((void**)&qkv,   g_qkv);
    float* att;   cudaGetSymbolAddress((void**)&att,   g_att);
    float* xt;    cudaGetSymbolAddress((void**)&xt,    g_xt);
    float* wqkvt; cudaGetSymbolAddress((void**)&wqkvt, g_wqkv_t);
    float* wprjt; cudaGetSymbolAddress((void**)&wprjt, g_wproj_t);

    cudaFuncSetAttribute(gemm_tf32_kernel,
                         cudaFuncAttributeMaxDynamicSharedMemorySize, GEMM_SMEM);
    cudaFuncSetAttribute(flash_mma_kernel,
                         cudaFuncAttributeMaxDynamicSharedMemorySize, FLASH_SMEM);

    const int M = BATCH * TSEQ;   // 4096

    // 0) tf32 pre-conversion (hoists all cvt out of GEMM hot loops)
    {
        const int n4x = M * CDIM / 4;            // 1,048,576
        const int n4q = CDIM * QKVN / 4;         //   786,432
        const int n4p = CDIM * CDIM / 4;         //   262,144
        tf32_convert_kernel<<<(n4x + 255) / 256, 256>>>(x, xt, n4x);
        tf32_convert_kernel<<<(n4q + 255) / 256, 256>>>(w_qkv, wqkvt, n4q);
        tf32_convert_kernel<<<(n4p + 255) / 256, 256>>>(w_proj, wprjt, n4p);
    }
    {   // 1) QKV projection (+ tf32 rounding, Q pre-scale in epilogue)
        dim3 grid(QKVN / 128, M / 128);   // (24, 32)
        gemm_tf32_kernel<<<grid, 256, GEMM_SMEM>>>(xt, wqkvt, b_qkv, qkv, M, QKVN, CDIM, 1);
    }
    {   // 2) Flash attention (tensor cores, cp.async double buffer)
        dim3 grid(TSEQ / 64, NHEADS, BATCH);   // (32, 16, 2)
        flash_mma_kernel<<<grid, 128, FLASH_SMEM>>>(qkv, att);
    }
    {   // 3) Output projection
        dim3 grid(CDIM / 128, M / 128);   // (8, 32)
        gemm_tf32_kernel<<<grid, 256, GEMM_SMEM>>>(att, wprjt, b_proj, out, M, CDIM, CDIM, 0);
    }
}

// round 8
// speedup vs baseline: 9.4709x; 2.1599x over previous
#include <cuda_runtime.h>
#include <cuda_fp16.h>
#include <cstdint>

// Problem constants
#define BATCH   2
#define TSEQ    2048
#define CDIM    1024
#define NHEADS  16
#define HDIM    64
#define QKVN    (3 * CDIM)  // 3072

// Scratch (allocation-free rule: __device__ globals)
__device__ __half g_qkv[(size_t)BATCH * TSEQ * 3 * CDIM];  // (B,T,3C) fp16, Q pre-scaled
__device__ __half g_att[(size_t)BATCH * TSEQ * CDIM];      // attn out fp16
__device__ __half g_xh[(size_t)BATCH * TSEQ * CDIM];       // x fp16
__device__ __half g_wqkvh[(size_t)CDIM * QKVN];            // w_qkv fp16
__device__ __half g_wprojh[(size_t)CDIM * CDIM];           // w_proj fp16

// ---------------------------------------------------------------------------
// Helpers
// ---------------------------------------------------------------------------
__device__ __forceinline__ uint32_t packh2(float lo, float hi) {
    uint32_t r;
    asm("cvt.rn.f16x2.f32 %0, %1, %2;" : "=r"(r) : "f"(hi), "f"(lo));
    return r;   // d.lo = cvt(lo), d.hi = cvt(hi)
}

__device__ __forceinline__ void mma16(float c[4], const uint32_t a[4], const uint32_t b[2]) {
    asm volatile(
        "mma.sync.aligned.m16n8k16.row.col.f32.f16.f16.f32 "
        "{%0,%1,%2,%3}, {%4,%5,%6,%7}, {%8,%9}, {%0,%1,%2,%3};\n"
        : "+f"(c[0]), "+f"(c[1]), "+f"(c[2]), "+f"(c[3])
        : "r"(a[0]), "r"(a[1]), "r"(a[2]), "r"(a[3]), "r"(b[0]), "r"(b[1]));
}

__device__ __forceinline__ void ldsm4(uint32_t r[4], uint32_t a) {
    asm volatile("ldmatrix.sync.aligned.m8n8.x4.shared.b16 {%0,%1,%2,%3}, [%4];"
                 : "=r"(r[0]), "=r"(r[1]), "=r"(r[2]), "=r"(r[3]) : "r"(a));
}
__device__ __forceinline__ void ldsm4t(uint32_t r[4], uint32_t a) {
    asm volatile("ldmatrix.sync.aligned.m8n8.x4.trans.shared.b16 {%0,%1,%2,%3}, [%4];"
                 : "=r"(r[0]), "=r"(r[1]), "=r"(r[2]), "=r"(r[3]) : "r"(a));
}

__device__ __forceinline__ void cpa16(uint32_t smaddr, const void* gptr) {
    asm volatile("cp.async.cg.shared.global [%0], [%1], 16;\n"
                 :: "r"(smaddr), "l"(gptr));
}
#define CP_COMMIT() asm volatile("cp.async.commit_group;\n" ::: "memory")
#define CP_WAITG(n) asm volatile("cp.async.wait_group %0;\n" :: "n"(n) : "memory")

// ---------------------------------------------------------------------------
// Pre-pass: fp32 -> fp16 (8 elems/thread)
// ---------------------------------------------------------------------------
__global__ __launch_bounds__(256) void f16_convert_kernel(
    const float* __restrict__ in, __half* __restrict__ out, int n8)
{
    const int i = blockIdx.x * blockDim.x + threadIdx.x;
    if (i < n8) {
        const float4 v0 = ((const float4*)in)[2 * i];
        const float4 v1 = ((const float4*)in)[2 * i + 1];
        uint4 u;
        u.x = packh2(v0.x, v0.y);  u.y = packh2(v0.z, v0.w);
        u.z = packh2(v1.x, v1.y);  u.w = packh2(v1.z, v1.w);
        ((uint4*)out)[i] = u;
    }
}

// ---------------------------------------------------------------------------
// FP16 tensor-core GEMM (fp32 accumulate):  C[M,N] = A[M,K] @ B[K,N] + bias
// 128x128x32 CTA tile, 8 warps (warp tile 32x64), 3-stage cp.async pipeline.
// A [m][k] halfs (stride 40) -> ldmatrix.x4 ; B [k][n] halfs (stride 136)
// -> ldmatrix.x4.trans. All strides conflict-free + 16B aligned.
// qkv_mode=1: C is half*, first CDIM cols (Q) pre-scaled by 0.125.
// qkv_mode=0: C is float* (final output).
// ---------------------------------------------------------------------------
#define ASTRH 40
#define ASZH  (128 * ASTRH)          // 5120 halfs
#define BSTRH 136
#define BSZH  (32 * BSTRH)           // 4352 halfs
#define STGH  (ASZH + BSZH)          // 9472 halfs/stage
#define GEMM_SMEM (3 * STGH * 2)     // 56832 bytes

__global__ __launch_bounds__(256, 2) void gemm_f16_kernel(
    const __half* __restrict__ A, const __half* __restrict__ B,
    const float* __restrict__ bias, void* __restrict__ Cout,
    int M, int N, int K, int qkv_mode)
{
    extern __shared__ __half sm[];
    const uint32_t smb = (uint32_t)__cvta_generic_to_shared(sm);

    const int tid  = threadIdx.x;
    const int lane = tid & 31;
    const int wid  = tid >> 5;
    const int g    = lane >> 2;
    const int tig  = lane & 3;
    const int wm   = (wid & 3) * 32;
    const int wn   = (wid >> 2) * 64;

    const int bm = blockIdx.y * 128;
    const int bn = blockIdx.x * 128;

    const int lrow = lane & 15;
    const int lhi8 = (lane >> 4) << 3;
    // per-lane ldmatrix byte offsets (relative to stage base)
    const uint32_t a_off = (uint32_t)(((wm + lrow) * ASTRH + lhi8) * 2);
    const uint32_t b_off = (uint32_t)((ASZH + lrow * BSTRH + wn + lhi8) * 2);

    float acc[2][8][4];
    #pragma unroll
    for (int mt = 0; mt < 2; mt++)
        #pragma unroll
        for (int nt = 0; nt < 8; nt++)
            #pragma unroll
            for (int i = 0; i < 4; i++) acc[mt][nt][i] = 0.0f;

    // A: 128x32 halfs = 512 x 16B ; B: 32x128 halfs = 512 x 16B
    #define ISSUE(s, k0)                                                       \
        do {                                                                   \
            const uint32_t sb = smb + (uint32_t)((s) * STGH * 2);              \
            _Pragma("unroll")                                                  \
            for (int c = tid; c < 512; c += 256) {                             \
                const int m_ = c >> 2, kc_ = (c & 3) << 3;                     \
                cpa16(sb + (uint32_t)((m_ * ASTRH + kc_) * 2),                 \
                      &A[(size_t)(bm + m_) * K + (k0) + kc_]);                 \
            }                                                                  \
            _Pragma("unroll")                                                  \
            for (int c = tid; c < 512; c += 256) {                             \
                const int k_ = c >> 4, nc_ = (c & 15) << 3;                    \
                cpa16(sb + (uint32_t)((ASZH + k_ * BSTRH + nc_) * 2),          \
                      &B[(size_t)((k0) + k_) * N + bn + nc_]);                 \
            }                                                                  \
        } while (0)

    const int ns = K / 32;
    ISSUE(0, 0);  CP_COMMIT();
    ISSUE(1, 32); CP_COMMIT();

    int cur = 0;
    for (int i = 0; i < ns; i++) {
        CP_WAITG(1);
        __syncthreads();

        if (i + 2 < ns) {
            const int s2 = (cur + 2 >= 3) ? cur - 1 : cur + 2;
            ISSUE(s2, (i + 2) * 32);
        }
        CP_COMMIT();

        const uint32_t sb = smb + (uint32_t)(cur * STGH * 2);
        const uint32_t ab = sb + a_off;
        const uint32_t bb = sb + b_off;

        #pragma unroll
        for (int kk = 0; kk < 32; kk += 16) {
            uint32_t a0[4], a1[4];
            ldsm4(a0, ab + (uint32_t)(kk * 2));                     // mt=0
            ldsm4(a1, ab + (uint32_t)(16 * ASTRH * 2 + kk * 2));    // mt=1
            #pragma unroll
            for (int j = 0; j < 4; j++) {
                uint32_t bf[4];   // b0,b1 of n-tile 2j ; b0,b1 of n-tile 2j+1
                ldsm4t(bf, bb + (uint32_t)(kk * BSTRH * 2 + j * 32));
                mma16(acc[0][2 * j],     a0, bf);
                mma16(acc[1][2 * j],     a1, bf);
                mma16(acc[0][2 * j + 1], a0, bf + 2);
                mma16(acc[1][2 * j + 1], a1, bf + 2);
            }
        }
        cur = (cur + 1 == 3) ? 0 : cur + 1;
    }
    #undef ISSUE

    // ---- epilogue ----
    #pragma unroll
    for (int mt = 0; mt < 2; mt++) {
        const int r0 = bm + wm + mt * 16 + g;
        #pragma unroll
        for (int nt = 0; nt < 8; nt++) {
            const int cc = bn + wn + nt * 8 + 2 * tig;
            const float2 bi = *(const float2*)&bias[cc];
            const float v00 = acc[mt][nt][0] + bi.x, v01 = acc[mt][nt][1] + bi.y;
            const float v10 = acc[mt][nt][2] + bi.x, v11 = acc[mt][nt][3] + bi.y;
            if (qkv_mode) {
                const float s = (cc < CDIM) ? 0.125f : 1.0f;  // Q pre-scale
                __half* C = (__half*)Cout;
                *(uint32_t*)&C[(size_t)r0 * N + cc]       = packh2(v00 * s, v01 * s);
                *(uint32_t*)&C[(size_t)(r0 + 8) * N + cc] = packh2(v10 * s, v11 * s);
            } else {
                float* C = (float*)Cout;
                float2 u0 = { v00, v01 }, u1 = { v10, v11 };
                *(float2*)&C[(size_t)r0 * N + cc]       = u0;
                *(float2*)&C[(size_t)(r0 + 8) * N + cc] = u1;
            }
        }
    }
}

// ---------------------------------------------------------------------------
// FP16 tensor-core flash attention, cp.async double-buffered K/V pipeline.
// CTA = (b, h, 64 q-rows), 4 warps x 16 rows. K-tile = 64 keys.
// QK^T: K [key][d] via ldmatrix (non-trans). PV: V [key][d] via ldmatrix.trans.
// P C-fragment == PV A-fragment layout -> just f16x2 packing, no shuffles.
// ---------------------------------------------------------------------------
#define KSTR 72                      // halfs per K/V row (64 + 8 pad)
#define KVH  (64 * KSTR)             // 4608 halfs per tensor
#define FBH  (2 * KVH)               // 9216 halfs per stage
#define NKT  (TSEQ / 64)
#define FLASH_SMEM (2 * FBH * 2)     // 36864 B

__global__ __launch_bounds__(128) void flash_f16_kernel(
    const __half* __restrict__ qkv, __half* __restrict__ out)
{
    extern __shared__ __half fsm[];
    const uint32_t smb = (uint32_t)__cvta_generic_to_shared(fsm);

    const int b   = blockIdx.z;
    const int h   = blockIdx.y;
    const int q0  = blockIdx.x * 64;
    const int tid = threadIdx.x;
    const int w    = tid >> 5;
    const int lane = tid & 31;
    const int g    = lane >> 2;
    const int tig  = lane & 3;

    // ---- stage Q through buf1's K region ----
    {
        __half* qs = fsm + FBH;
        for (int i = tid; i < 512; i += 128) {
            const int row = i >> 3;
            const int c8  = (i & 7) << 3;
            *(uint4*)&qs[row * KSTR + c8] =
                *(const uint4*)&qkv[((size_t)(b * TSEQ + q0 + row)) * QKVN + h * HDIM + c8];
        }
    }
    __syncthreads();

    // Q fragments: 4 d-steps of m16k16 (non-trans ldmatrix)
    const int lrow = lane & 15;
    const int lhi8 = (lane >> 4) << 3;
    uint32_t qf[4][4];
    {
        const uint32_t qb = smb + (uint32_t)(FBH * 2) +
                            (uint32_t)(((w * 16 + lrow) * KSTR + lhi8) * 2);
        #pragma unroll
        for (int ds = 0; ds < 4; ds++) ldsm4(qf[ds], qb + (uint32_t)(ds * 32));
    }
    __syncthreads();

    // per-lane ldmatrix offsets
    const int krow_off = ((lane >> 4) << 3) + (lane & 7);      // K (non-trans)
    const int kdsel    = ((lane >> 3) & 1) << 3;
    const int vrow_off = (((lane >> 3) & 1) << 3) + (lane & 7); // V (trans)
    const int vdsel    = (lane >> 4) << 3;

    float o[8][4];
    #pragma unroll
    for (int nt = 0; nt < 8; nt++)
        #pragma unroll
        for (int i = 0; i < 4; i++) o[nt][i] = 0.0f;
    float m0 = -1e30f, m1 = -1e30f, l0 = 0.0f, l1 = 0.0f;

    #define STAGE_KV(buf_idx, kt)                                              \
        do {                                                                   \
            const uint32_t kb_ = smb + (uint32_t)((buf_idx) * FBH * 2);        \
            const uint32_t vb_ = kb_ + (uint32_t)(KVH * 2);                    \
            for (int i = tid; i < 512; i += 128) {                             \
                const int row = i >> 3;                                        \
                const int c8  = (i & 7) << 3;                                  \
                const size_t base =                                            \
                    ((size_t)(b * TSEQ + (kt) + row)) * QKVN + h * HDIM + c8;  \
                cpa16(kb_ + (uint32_t)((row * KSTR + c8) * 2),                 \
                      &qkv[base + CDIM]);                                      \
                cpa16(vb_ + (uint32_t)((row * KSTR + c8) * 2),                 \
                      &qkv[base + 2 * CDIM]);                                  \
            }                                                                  \
        } while (0)

    STAGE_KV(0, 0);
    CP_COMMIT();

    for (int it = 0; it < NKT; it++) {
        if (it + 1 < NKT) {
            STAGE_KV((it + 1) & 1, (it + 1) * 64);
            CP_COMMIT();
            CP_WAITG(1);
        } else {
            CP_WAITG(0);
        }
        __syncthreads();

        const uint32_t ksb = smb + (uint32_t)((it & 1) * FBH * 2);
        const uint32_t vsb = ksb + (uint32_t)(KVH * 2);
        const uint32_t kbase = ksb + (uint32_t)((krow_off * KSTR + kdsel) * 2);
        const uint32_t vbase = vsb + (uint32_t)((vrow_off * KSTR + vdsel) * 2);

        // ---- S = Q @ K^T ----
        float sv[8][4];
        #pragma unroll
        for (int nt = 0; nt < 8; nt++)
            #pragma unroll
            for (int i = 0; i < 4; i++) sv[nt][i] = 0.0f;

        #pragma unroll
        for (int ds = 0; ds < 4; ds++) {
            #pragma unroll
            for (int j = 0; j < 4; j++) {
                uint32_t bf[4];   // b0,b1 of key-tile 2j ; b0,b1 of 2j+1
                ldsm4(bf, kbase + (uint32_t)((j * 16 * KSTR + ds * 16) * 2));
                mma16(sv[2 * j],     qf[ds], bf);
                mma16(sv[2 * j + 1], qf[ds], bf + 2);
            }
        }

        // ---- online softmax (rows g and g+8) ----
        float rmax0 = -1e30f, rmax1 = -1e30f;
        #pragma unroll
        for (int nt = 0; nt < 8; nt++) {
            rmax0 = fmaxf(rmax0, fmaxf(sv[nt][0], sv[nt][1]));
            rmax1 = fmaxf(rmax1, fmaxf(sv[nt][2], sv[nt][3]));
        }
        rmax0 = fmaxf(rmax0, __shfl_xor_sync(0xffffffffu, rmax0, 1));
        rmax0 = fmaxf(rmax0, __shfl_xor_sync(0xffffffffu, rmax0, 2));
        rmax1 = fmaxf(rmax1, __shfl_xor_sync(0xffffffffu, rmax1, 1));
        rmax1 = fmaxf(rmax1, __shfl_xor_sync(0xffffffffu, rmax1, 2));

        const float mn0 = fmaxf(m0, rmax0);
        const float mn1 = fmaxf(m1, rmax1);
        const float cr0 = __expf(m0 - mn0);
        const float cr1 = __expf(m1 - mn1);
        m0 = mn0; m1 = mn1;

        float ls0 = 0.0f, ls1 = 0.0f;
        uint32_t pv[8][2];
        #pragma unroll
        for (int nt = 0; nt < 8; nt++) {
            const float p0 = __expf(sv[nt][0] - mn0);
            const float p1 = __expf(sv[nt][1] - mn0);
            const float p2 = __expf(sv[nt][2] - mn1);
            const float p3 = __expf(sv[nt][3] - mn1);
            ls0 += p0 + p1;  ls1 += p2 + p3;
            pv[nt][0] = packh2(p0, p1);   // P C-frag == PV A-frag layout
            pv[nt][1] = packh2(p2, p3);
        }
        ls0 += __shfl_xor_sync(0xffffffffu, ls0, 1);
        ls0 += __shfl_xor_sync(0xffffffffu, ls0, 2);
        ls1 += __shfl_xor_sync(0xffffffffu, ls1, 1);
        ls1 += __shfl_xor_sync(0xffffffffu, ls1, 2);
        l0 = l0 * cr0 + ls0;
        l1 = l1 * cr1 + ls1;

        #pragma unroll
        for (int nt = 0; nt < 8; nt++) {
            o[nt][0] *= cr0; o[nt][1] *= cr0;
            o[nt][2] *= cr1; o[nt][3] *= cr1;
        }

        // ---- O += P @ V ----
        #pragma unroll
        for (int j = 0; j < 4; j++) {
            const uint32_t a[4] = { pv[2 * j][0], pv[2 * j][1],
                                    pv[2 * j + 1][0], pv[2 * j + 1][1] };
            #pragma unroll
            for (int t = 0; t < 4; t++) {
                uint32_t bf[4];   // b0,b1 of d-tile 2t ; b0,b1 of 2t+1
                ldsm4t(bf, vbase + (uint32_t)((j * 16 * KSTR + t * 16) * 2));
                mma16(o[2 * t],     a, bf);
                mma16(o[2 * t + 1], a, bf + 2);
            }
        }
        __syncthreads();
    }
    #undef STAGE_KV

    // ---- epilogue: fp16 att for proj GEMM ----
    const float i0 = 1.0f / l0;
    const float i1 = 1.0f / l1;
    const int r0 = q0 + w * 16 + g;
    #pragma unroll
    for (int nt = 0; nt < 8; nt++) {
        const int cc = h * HDIM + nt * 8 + 2 * tig;
        *(uint32_t*)&out[((size_t)(b * TSEQ + r0)) * CDIM + cc] =
            packh2(o[nt][0] * i0, o[nt][1] * i0);
        *(uint32_t*)&out[((size_t)(b * TSEQ + r0 + 8)) * CDIM + cc] =
            packh2(o[nt][2] * i1, o[nt][3] * i1);
    }
}

// ---------------------------------------------------------------------------
// Launch
// ---------------------------------------------------------------------------
extern "C" void kernel_launch(void* const* d_in, const int* in_sizes, int n_in,
                              void* d_out, int out_size)
{
    const float* x      = (const float*)d_in[0];
    const float* w_qkv  = (const float*)d_in[1];
    const float* b_qkv  = (const float*)d_in[2];
    const float* w_proj = (const float*)d_in[3];
    const float* b_proj = (const float*)d_in[4];
    float* out = (float*)d_out;

    __half* qkv;   cudaGetSymbolAddress((void**)&qkv,   g_qkv);
    __half* att;   cudaGetSymbolAddress((void**)&att,   g_att);
    __half* xh;    cudaGetSymbolAddress((void**)&xh,    g_xh);
    __half* wqkvh; cudaGetSymbolAddress((void**)&wqkvh, g_wqkvh);
    __half* wprjh; cudaGetSymbolAddress((void**)&wprjh, g_wprojh);

    cudaFuncSetAttribute(gemm_f16_kernel,
                         cudaFuncAttributeMaxDynamicSharedMemorySize, GEMM_SMEM);
    cudaFuncSetAttribute(flash_f16_kernel,
                         cudaFuncAttributeMaxDynamicSharedMemorySize, FLASH_SMEM);

    const int M = BATCH * TSEQ;   // 4096

    // 0) fp16 pre-conversion
    {
        const int n8x = M * CDIM / 8;        // 524288
        const int n8q = CDIM * QKVN / 8;     // 393216
        const int n8p = CDIM * CDIM / 8;     // 131072
        f16_convert_kernel<<<(n8x + 255) / 256, 256>>>(x, xh, n8x);
        f16_convert_kernel<<<(n8q + 255) / 256, 256>>>(w_qkv, wqkvh, n8q);
        f16_convert_kernel<<<(n8p + 255) / 256, 256>>>(w_proj, wprjh, n8p);
    }
    {   // 1) QKV projection (fp16 out, Q pre-scaled)
        dim3 grid(QKVN / 128, M / 128);   // (24, 32)
        gemm_f16_kernel<<<grid, 256, GEMM_SMEM>>>(xh, wqkvh, b_qkv, qkv, M, QKVN, CDIM, 1);
    }
    {   // 2) Flash attention (fp16 tensor cores)
        dim3 grid(TSEQ / 64, NHEADS, BATCH);   // (32, 16, 2)
        flash_f16_kernel<<<grid, 128, FLASH_SMEM>>>(qkv, att);
    }
    {   // 3) Output projection (fp32 out)
        dim3 grid(CDIM / 128, M / 128);   // (8, 32)
        gemm_f16_kernel<<<grid, 256, GEMM_SMEM>>>(att, wprjh, b_proj, out, M, CDIM, CDIM, 0);
    }
}